// round 12
// baseline (speedup 1.0000x reference)
#include <cuda_runtime.h>
#include <cuda_fp16.h>
#include <cstdint>

// Problem constants
#define S_DIM 256
#define B_DIM 128
#define D_DIM 768
#define L_DIM 200
#define V_DIM 8
#define M_DIM (S_DIM * B_DIM)   // 32768
#define N_DIM (L_DIM * V_DIM)   // 1600

// GEMM tiling
#define BM 128                  // rows per CTA (one s; local row == batch b)
#define BN 64                   // cols per CTA (8 whole labels)
#define KC 64                   // fp16 k per chunk -> 128-byte rows
#define NCHUNK (D_DIM / KC)     // 12
#define NSTAGE 3
#define NTHREADS 128            // 4 warps, 2x2 warp grid, 64x32 warp tile

#define NKB (D_DIM / 16)        // 48 k16-blocks
#define NNB (N_DIM / 8)         // 200 n8-blocks

#define A_BYTES (BM * KC * 2)   // 16384 (A-only stage)
#define SMEM_TOTAL (NSTAGE * A_BYTES)   // 49152 -> 4 CTAs/SM by smem

// Scratch (no runtime allocation allowed)
__device__ __half g_A[(size_t)M_DIM * D_DIM];     // unit-normalized embed, ~50 MB
__device__ __half g_B[(size_t)N_DIM * D_DIM];     // unit-normalized labels, ~2.4 MB
__device__ uint2  g_Bf[(size_t)NNB * NKB * 32];   // B in mma-fragment order, ~2.5 MB

// ---------------- PTX helpers (base PTX only) ----------------
__device__ __forceinline__ uint32_t smem_u32(const void* p) {
    uint32_t a;
    asm("{ .reg .u64 t; cvta.to.shared.u64 t, %1; cvt.u32.u64 %0, t; }"
        : "=r"(a) : "l"(p));
    return a;
}

#define CP_ASYNC16(s, g) \
    asm volatile("cp.async.cg.shared.global [%0], [%1], 16;" \
                 :: "r"(s), "l"(g) : "memory")
#define CP_COMMIT() asm volatile("cp.async.commit_group;" ::: "memory")
#define CP_WAIT(n)  asm volatile("cp.async.wait_group %0;" :: "n"(n) : "memory")

#define LDMATRIX_X4(r, addr) \
    asm volatile("ldmatrix.sync.aligned.m8n8.x4.shared.b16 {%0,%1,%2,%3}, [%4];" \
                 : "=r"((r)[0]), "=r"((r)[1]), "=r"((r)[2]), "=r"((r)[3]) \
                 : "r"(addr))

#define MMA16816(d, a, b0, b1) \
    asm volatile("mma.sync.aligned.m16n8k16.row.col.f32.f16.f16.f32 " \
                 "{%0,%1,%2,%3}, {%4,%5,%6,%7}, {%8,%9}, {%0,%1,%2,%3};" \
                 : "+f"((d)[0]), "+f"((d)[1]), "+f"((d)[2]), "+f"((d)[3]) \
                 : "r"((a)[0]), "r"((a)[1]), "r"((a)[2]), "r"((a)[3]), \
                   "r"(b0), "r"(b1))

// Sign-aware float atomic max (out initialized to -1.0; values in [-1, 1])
__device__ __forceinline__ void atomicMaxF(float* addr, float v) {
    if (v >= 0.0f) atomicMax((int*)addr, __float_as_int(v));
    else           atomicMin((unsigned int*)addr, __float_as_uint(v));
}

// Swizzled byte offset inside the A tile: row r (128B rows), 16B chunk c 0..7
__device__ __forceinline__ uint32_t swz(int r, int c) {
    return (uint32_t)(r * 128 + ((c ^ (r & 7)) << 4));
}

// ---------------- aux kernels ----------------
__global__ void init_out_kernel(float* out) {
    int i = blockIdx.x * blockDim.x + threadIdx.x;
    if (i < B_DIM * L_DIM) out[i] = -1.0f;
}

// One warp per row: fp32 -> unit-norm fp16 (norms ~27.7, eps clamp never active)
__global__ void normalize_kernel(const float* __restrict__ x,
                                 __half* __restrict__ y, int rows) {
    int w = (blockIdx.x * blockDim.x + threadIdx.x) >> 5;
    int lane = threadIdx.x & 31;
    if (w >= rows) return;
    const float4* p = reinterpret_cast<const float4*>(x + (size_t)w * D_DIM);
    float4 v[6];
    float s = 0.0f;
#pragma unroll
    for (int j = 0; j < 6; j++) {
        v[j] = p[lane + 32 * j];
        s += v[j].x * v[j].x + v[j].y * v[j].y + v[j].z * v[j].z + v[j].w * v[j].w;
    }
#pragma unroll
    for (int o = 16; o > 0; o >>= 1) s += __shfl_xor_sync(0xffffffffu, s, o);
    float inv = 1.0f / sqrtf(s);
#pragma unroll
    for (int j = 0; j < 6; j++) {
        __half2 h0 = __floats2half2_rn(v[j].x * inv, v[j].y * inv);
        __half2 h1 = __floats2half2_rn(v[j].z * inv, v[j].w * inv);
        size_t base = (size_t)w * D_DIM + (size_t)(lane + 32 * j) * 4;
        *reinterpret_cast<__half2*>(y + base)     = h0;
        *reinterpret_cast<__half2*>(y + base + 2) = h1;
    }
}

// Reshuffle g_B into mma-fragment order:
// for block (bn, bk), lane l: b0 = B[bn*8 + l/4][bk*16 + 2*(l&3) .. +1]
//                             b1 = same row, k + 8  (matches ldmatrix t0..t3)
__global__ void shuffle_b_kernel() {
    int i = blockIdx.x * blockDim.x + threadIdx.x;
    if (i >= NNB * NKB * 32) return;
    int lane = i & 31;
    int bk = (i >> 5) % NKB;
    int bn = i / (NKB * 32);
    const __half* row = g_B + (size_t)(bn * 8 + (lane >> 2)) * D_DIM;
    int k0 = bk * 16 + (lane & 3) * 2;
    uint32_t b0 = *reinterpret_cast<const uint32_t*>(row + k0);
    uint32_t b1 = *reinterpret_cast<const uint32_t*>(row + k0 + 8);
    g_Bf[i] = make_uint2(b0, b1);
}

// ---------------- fused HMMA GEMM + max epilogue ----------------
// A via 3-stage cp.async smem + ldmatrix; B fragments via direct LDG.64 from
// the L2-resident fragment-major copy. One barrier per chunk.
__global__ __launch_bounds__(NTHREADS)
void gemm_mma_kernel(const __half* __restrict__ A, float* __restrict__ out) {
    extern __shared__ char smem[];
    const uint32_t sb = smem_u32(smem);
    const int tid = threadIdx.x;
    const int wid = tid >> 5;
    const int lane = tid & 31;
    const int wm = wid >> 1;            // 0..1  (m: 64-row slab)
    const int wn = wid & 1;             // 0..1  (n: 32-col slab)
    const int m0 = blockIdx.y * BM;
    const int n0 = blockIdx.x * BN;
    const int l0 = blockIdx.x * (BN / V_DIM);

    // per-warp B fragment base: block (bn0 + ni), lane-resident
    const uint2* __restrict__ Bf = g_Bf;
    const int bn0 = blockIdx.x * 8 + wn * 4;
    const size_t bfbase = (size_t)bn0 * NKB * 32 + lane;

    auto loadA = [&](int stage, int c) {
        const uint32_t base = sb + stage * A_BYTES;
#pragma unroll
        for (int j = 0; j < 8; j++) {                  // A: 128 rows x 128B
            int f = j * NTHREADS + tid;
            int r = f >> 3, cc = f & 7;
            const __half* g = A + (size_t)(m0 + r) * D_DIM + c * KC + cc * 8;
            CP_ASYNC16(base + swz(r, cc), g);
        }
    };

    float acc[4][4][4];
#pragma unroll
    for (int mi = 0; mi < 4; mi++)
#pragma unroll
        for (int ni = 0; ni < 4; ni++)
#pragma unroll
            for (int e = 0; e < 4; e++) acc[mi][ni][e] = 0.0f;

    loadA(0, 0); CP_COMMIT();
    loadA(1, 1); CP_COMMIT();

    const int t = lane >> 3;            // ldmatrix tile index 0..3
    const int lr = lane & 7;            // row within 8-row tile
    int stage = 0;

#pragma unroll 1
    for (int c = 0; c < NCHUNK; c++) {
        // wait for A chunk c (c+1 may remain in flight)
        if (c + 2 < NCHUNK) { CP_WAIT(1); } else { CP_WAIT(0); }
        __syncthreads();   // chunk c's smem visible; stage (c+2)%3 is free
        if (c + 2 < NCHUNK) {
            int s2 = stage + 2; if (s2 >= NSTAGE) s2 -= NSTAGE;
            loadA(s2, c + 2); CP_COMMIT();
        }

        const uint32_t ab = sb + stage * A_BYTES;
#pragma unroll
        for (int ks = 0; ks < 4; ks++) {          // four k16 steps per chunk
            // B fragments: 4 independent LDG.64 from L2 (fragment-major)
            uint2 bf[4];
#pragma unroll
            for (int ni = 0; ni < 4; ni++)
                bf[ni] = Bf[bfbase + (size_t)(ni * NKB + c * 4 + ks) * 32];

            uint32_t afr[4][4];
#pragma unroll
            for (int mi = 0; mi < 4; mi++) {
                int r = wm * 64 + mi * 16 + lr + ((t & 1) << 3);
                int cc = ks * 2 + (t >> 1);
                LDMATRIX_X4(afr[mi], ab + swz(r, cc));
            }
#pragma unroll
            for (int mi = 0; mi < 4; mi++)
#pragma unroll
                for (int ni = 0; ni < 4; ni++)
                    MMA16816(acc[mi][ni], afr[mi], bf[ni].x, bf[ni].y);
        }
        if (++stage >= NSTAGE) stage = 0;
    }

    // ---- epilogue: each n8 fragment == one label; reduce v via shfl ----
    const int g  = lane >> 2;           // fragment row group 0..7
    const int tq = lane & 3;            // v-pair owner 0..3
#pragma unroll
    for (int mi = 0; mi < 4; mi++) {
        const int b0 = wm * 64 + mi * 16 + g;      // local row == batch b
#pragma unroll
        for (int ni = 0; ni < 4; ni++) {
            float mx0 = fmaxf(acc[mi][ni][0], acc[mi][ni][1]);   // row b0
            float mx1 = fmaxf(acc[mi][ni][2], acc[mi][ni][3]);   // row b0+8
#pragma unroll
            for (int o = 1; o < 4; o <<= 1) {      // collect all 8 v of this label
                mx0 = fmaxf(mx0, __shfl_xor_sync(0xffffffffu, mx0, o));
                mx1 = fmaxf(mx1, __shfl_xor_sync(0xffffffffu, mx1, o));
            }
            if (tq == 0) {
                int l = l0 + wn * 4 + ni;
                atomicMaxF(out + b0 * L_DIM + l, mx0);
                atomicMaxF(out + (b0 + 8) * L_DIM + l, mx1);
            }
        }
    }
}

extern "C" void kernel_launch(void* const* d_in, const int* in_sizes, int n_in,
                              void* d_out, int out_size) {
    const float* embed = (const float*)d_in[0];   // [256,128,768]
    const float* label = (const float*)d_in[1];   // [200,8,768]
    float* out = (float*)d_out;                   // [128,200]

    __half *d_A, *d_B;
    cudaGetSymbolAddress((void**)&d_A, g_A);
    cudaGetSymbolAddress((void**)&d_B, g_B);

    (void)cudaFuncSetAttribute(gemm_mma_kernel,
                               cudaFuncAttributeMaxDynamicSharedMemorySize,
                               SMEM_TOTAL);

    init_out_kernel<<<(B_DIM * L_DIM + 255) / 256, 256>>>(out);
    normalize_kernel<<<M_DIM / 8, 256>>>(embed, d_A, M_DIM);   // 8 warps/block
    normalize_kernel<<<N_DIM / 8, 256>>>(label, d_B, N_DIM);
    shuffle_b_kernel<<<(NNB * NKB * 32 + 255) / 256, 256>>>();

    dim3 grid(N_DIM / BN, M_DIM / BM);   // (25, 256) = 6400 CTAs
    gemm_mma_kernel<<<grid, NTHREADS, SMEM_TOTAL>>>(d_A, out);
}

// round 13
// speedup vs baseline: 1.0157x; 1.0157x over previous
#include <cuda_runtime.h>
#include <cuda_fp16.h>
#include <cstdint>

// Problem constants
#define S_DIM 256
#define B_DIM 128
#define D_DIM 768
#define L_DIM 200
#define V_DIM 8
#define M_DIM (S_DIM * B_DIM)   // 32768
#define N_DIM (L_DIM * V_DIM)   // 1600

// GEMM tiling
#define BM 128                  // rows per CTA (one s; local row == batch b)
#define BN 64                   // cols per CTA (8 whole labels)
#define KC 64                   // fp16 k per chunk -> 128-byte rows
#define NCHUNK (D_DIM / KC)     // 12
#define NSTAGE 3
#define NTHREADS 128            // 4 warps, 2x2 warp grid, 64x32 warp tile

#define NKB (D_DIM / 16)        // 48 k16-blocks
#define NNB (N_DIM / 8)         // 200 n8-blocks

#define A_BYTES (BM * KC * 2)   // 16384 (A-only stage)
#define SMEM_TOTAL (NSTAGE * A_BYTES)   // 49152 -> 4 CTAs/SM by smem

// Scratch (no runtime allocation allowed)
__device__ __half g_A[(size_t)M_DIM * D_DIM];     // unit-normalized embed
__device__ __half g_B[(size_t)N_DIM * D_DIM];     // unit-normalized labels
__device__ uint2  g_Bf[(size_t)NNB * NKB * 32];   // B in mma-fragment order

// ---------------- PTX helpers (base PTX only) ----------------
__device__ __forceinline__ uint32_t smem_u32(const void* p) {
    uint32_t a;
    asm("{ .reg .u64 t; cvta.to.shared.u64 t, %1; cvt.u32.u64 %0, t; }"
        : "=r"(a) : "l"(p));
    return a;
}

#define CP_ASYNC16(s, g) \
    asm volatile("cp.async.cg.shared.global [%0], [%1], 16;" \
                 :: "r"(s), "l"(g) : "memory")
#define CP_COMMIT() asm volatile("cp.async.commit_group;" ::: "memory")
#define CP_WAIT(n)  asm volatile("cp.async.wait_group %0;" :: "n"(n) : "memory")

#define LDMATRIX_X4(r, addr) \
    asm volatile("ldmatrix.sync.aligned.m8n8.x4.shared.b16 {%0,%1,%2,%3}, [%4];" \
                 : "=r"((r)[0]), "=r"((r)[1]), "=r"((r)[2]), "=r"((r)[3]) \
                 : "r"(addr))

#define MMA16816(d, a, b0, b1) \
    asm volatile("mma.sync.aligned.m16n8k16.row.col.f32.f16.f16.f32 " \
                 "{%0,%1,%2,%3}, {%4,%5,%6,%7}, {%8,%9}, {%0,%1,%2,%3};" \
                 : "+f"((d)[0]), "+f"((d)[1]), "+f"((d)[2]), "+f"((d)[3]) \
                 : "r"((a)[0]), "r"((a)[1]), "r"((a)[2]), "r"((a)[3]), \
                   "r"(b0), "r"(b1))

// Sign-aware float atomic max (out initialized to -1.0; values in [-1, 1])
__device__ __forceinline__ void atomicMaxF(float* addr, float v) {
    if (v >= 0.0f) atomicMax((int*)addr, __float_as_int(v));
    else           atomicMin((unsigned int*)addr, __float_as_uint(v));
}

// Swizzled byte offset inside the A tile: row r (128B rows), 16B chunk c 0..7
__device__ __forceinline__ uint32_t swz(int r, int c) {
    return (uint32_t)(r * 128 + ((c ^ (r & 7)) << 4));
}

// ---------------- aux kernels ----------------
// One warp per row: fp32 -> unit-norm fp16 (norms ~27.7, eps clamp never active)
__global__ void normalize_kernel(const float* __restrict__ x,
                                 __half* __restrict__ y, int rows) {
    int w = (blockIdx.x * blockDim.x + threadIdx.x) >> 5;
    int lane = threadIdx.x & 31;
    if (w >= rows) return;
    const float4* p = reinterpret_cast<const float4*>(x + (size_t)w * D_DIM);
    float4 v[6];
    float s = 0.0f;
#pragma unroll
    for (int j = 0; j < 6; j++) {
        v[j] = p[lane + 32 * j];
        s += v[j].x * v[j].x + v[j].y * v[j].y + v[j].z * v[j].z + v[j].w * v[j].w;
    }
#pragma unroll
    for (int o = 16; o > 0; o >>= 1) s += __shfl_xor_sync(0xffffffffu, s, o);
    float inv = 1.0f / sqrtf(s);
#pragma unroll
    for (int j = 0; j < 6; j++) {
        __half2 h0 = __floats2half2_rn(v[j].x * inv, v[j].y * inv);
        __half2 h1 = __floats2half2_rn(v[j].z * inv, v[j].w * inv);
        size_t base = (size_t)w * D_DIM + (size_t)(lane + 32 * j) * 4;
        *reinterpret_cast<__half2*>(y + base)     = h0;
        *reinterpret_cast<__half2*>(y + base + 2) = h1;
    }
}

// Reshuffle g_B into mma-fragment order (mapping verified in R12: identical
// rel_err to the ldmatrix path). Also initializes out to -1.
__global__ void shuffle_b_kernel(float* __restrict__ out) {
    int i = blockIdx.x * blockDim.x + threadIdx.x;
    if (i < B_DIM * L_DIM) out[i] = -1.0f;
    if (i >= NNB * NKB * 32) return;
    int lane = i & 31;
    int bk = (i >> 5) % NKB;
    int bn = i / (NKB * 32);
    const __half* row = g_B + (size_t)(bn * 8 + (lane >> 2)) * D_DIM;
    int k0 = bk * 16 + (lane & 3) * 2;
    uint32_t b0 = *reinterpret_cast<const uint32_t*>(row + k0);
    uint32_t b1 = *reinterpret_cast<const uint32_t*>(row + k0 + 8);
    g_Bf[i] = make_uint2(b0, b1);
}

// ---------------- fused HMMA GEMM + max epilogue ----------------
// A via 3-stage cp.async smem + ldmatrix (one barrier per chunk);
// B fragments from L2 (fragment-major), register-prefetched one k-step ahead.
__global__ __launch_bounds__(NTHREADS)
void gemm_mma_kernel(const __half* __restrict__ A, float* __restrict__ out) {
    extern __shared__ char smem[];
    const uint32_t sb = smem_u32(smem);
    const int tid = threadIdx.x;
    const int wid = tid >> 5;
    const int lane = tid & 31;
    const int wm = wid >> 1;            // 0..1  (m: 64-row slab)
    const int wn = wid & 1;             // 0..1  (n: 32-col slab)
    const int m0 = blockIdx.y * BM;
    const int l0 = blockIdx.x * (BN / V_DIM);

    // per-warp B fragment base: 4 n8-blocks starting at bn0, lane-resident
    const uint2* __restrict__ Bf = g_Bf;
    const int bn0 = blockIdx.x * 8 + wn * 4;
    const uint2* bfp = Bf + (size_t)bn0 * NKB * 32 + lane;
    // address of fragment (ni, kidx): bfp[(ni*NKB + kidx)*32]

    auto loadA = [&](int stage, int c) {
        const uint32_t base = sb + stage * A_BYTES;
#pragma unroll
        for (int j = 0; j < 8; j++) {                  // A: 128 rows x 128B
            int f = j * NTHREADS + tid;
            int r = f >> 3, cc = f & 7;
            const __half* g = A + (size_t)(m0 + r) * D_DIM + c * KC + cc * 8;
            CP_ASYNC16(base + swz(r, cc), g);
        }
    };

    float acc[4][4][4];
#pragma unroll
    for (int mi = 0; mi < 4; mi++)
#pragma unroll
        for (int ni = 0; ni < 4; ni++)
#pragma unroll
            for (int e = 0; e < 4; e++) acc[mi][ni][e] = 0.0f;

    loadA(0, 0); CP_COMMIT();
    loadA(1, 1); CP_COMMIT();

    // prime the B fragment pipeline with kidx = 0
    uint2 bcur[4], bnx[4];
#pragma unroll
    for (int ni = 0; ni < 4; ni++) bcur[ni] = bfp[(size_t)(ni * NKB) * 32];

    const int t = lane >> 3;            // ldmatrix tile index 0..3
    const int lr = lane & 7;            // row within 8-row tile
    int stage = 0;

#pragma unroll 1
    for (int c = 0; c < NCHUNK; c++) {
        // wait for A chunk c (c+1 may remain in flight)
        if (c + 2 < NCHUNK) { CP_WAIT(1); } else { CP_WAIT(0); }
        __syncthreads();   // all warps past chunk c-1 -> stage (c+2)%3 is free
        if (c + 2 < NCHUNK) {
            int s2 = stage + 2; if (s2 >= NSTAGE) s2 -= NSTAGE;
            loadA(s2, c + 2); CP_COMMIT();
        }

        const uint32_t ab = sb + stage * A_BYTES;
#pragma unroll
        for (int ks = 0; ks < 4; ks++) {          // four k16 steps per chunk
            // prefetch B fragments for the NEXT k-step (clamped at the end)
            int kidx = c * 4 + ks;
            int kn = (kidx + 1 < NKB) ? (kidx + 1) : kidx;
#pragma unroll
            for (int ni = 0; ni < 4; ni++)
                bnx[ni] = bfp[(size_t)(ni * NKB + kn) * 32];

            uint32_t afr[4][4];
#pragma unroll
            for (int mi = 0; mi < 4; mi++) {
                int r = wm * 64 + mi * 16 + lr + ((t & 1) << 3);
                int cc = ks * 2 + (t >> 1);
                LDMATRIX_X4(afr[mi], ab + swz(r, cc));
            }
#pragma unroll
            for (int mi = 0; mi < 4; mi++)
#pragma unroll
                for (int ni = 0; ni < 4; ni++)
                    MMA16816(acc[mi][ni], afr[mi], bcur[ni].x, bcur[ni].y);
#pragma unroll
            for (int ni = 0; ni < 4; ni++) bcur[ni] = bnx[ni];
        }
        if (++stage >= NSTAGE) stage = 0;
    }

    // ---- epilogue: each n8 fragment == one label; reduce v via shfl ----
    const int g  = lane >> 2;           // fragment row group 0..7
    const int tq = lane & 3;            // v-pair owner 0..3
#pragma unroll
    for (int mi = 0; mi < 4; mi++) {
        const int b0 = wm * 64 + mi * 16 + g;      // local row == batch b
#pragma unroll
        for (int ni = 0; ni < 4; ni++) {
            float mx0 = fmaxf(acc[mi][ni][0], acc[mi][ni][1]);   // row b0
            float mx1 = fmaxf(acc[mi][ni][2], acc[mi][ni][3]);   // row b0+8
#pragma unroll
            for (int o = 1; o < 4; o <<= 1) {      // collect all 8 v of this label
                mx0 = fmaxf(mx0, __shfl_xor_sync(0xffffffffu, mx0, o));
                mx1 = fmaxf(mx1, __shfl_xor_sync(0xffffffffu, mx1, o));
            }
            if (tq == 0) {
                int l = l0 + wn * 4 + ni;
                atomicMaxF(out + b0 * L_DIM + l, mx0);
                atomicMaxF(out + (b0 + 8) * L_DIM + l, mx1);
            }
        }
    }
}

extern "C" void kernel_launch(void* const* d_in, const int* in_sizes, int n_in,
                              void* d_out, int out_size) {
    const float* embed = (const float*)d_in[0];   // [256,128,768]
    const float* label = (const float*)d_in[1];   // [200,8,768]
    float* out = (float*)d_out;                   // [128,200]

    __half *d_A, *d_B;
    cudaGetSymbolAddress((void**)&d_A, g_A);
    cudaGetSymbolAddress((void**)&d_B, g_B);

    (void)cudaFuncSetAttribute(gemm_mma_kernel,
                               cudaFuncAttributeMaxDynamicSharedMemorySize,
                               SMEM_TOTAL);

    normalize_kernel<<<N_DIM / 8, 256>>>(label, d_B, N_DIM);
    shuffle_b_kernel<<<(NNB * NKB * 32 + 255) / 256, 256>>>(out);  // + out init
    normalize_kernel<<<M_DIM / 8, 256>>>(embed, d_A, M_DIM);

    dim3 grid(N_DIM / BN, M_DIM / BM);   // (25, 256) = 6400 CTAs
    gemm_mma_kernel<<<grid, NTHREADS, SMEM_TOTAL>>>(d_A, out);
}

// round 14
// speedup vs baseline: 1.1840x; 1.1657x over previous
#include <cuda_runtime.h>
#include <cuda_fp16.h>
#include <cstdint>

// Problem constants
#define S_DIM 256
#define B_DIM 128
#define D_DIM 768
#define L_DIM 200
#define V_DIM 8
#define M_DIM (S_DIM * B_DIM)   // 32768
#define N_DIM (L_DIM * V_DIM)   // 1600

// GEMM tiling
#define BM 128                  // rows per CTA (one s; local row == batch b)
#define BN 64                   // cols per CTA (8 whole labels)
#define KC 64                   // fp16 k per chunk -> 128-byte rows
#define NCHUNK (D_DIM / KC)     // 12
#define NTHREADS 128            // 4 warps, 2x2 warp grid, 64x32 warp tile

#define A_BYTES (BM * KC * 2)   // 16384
#define B_BYTES (BN * KC * 2)   //  8192
#define BUF_BYTES (A_BYTES + B_BYTES)          // 24576
#define SMEM_TOTAL (2 * BUF_BYTES)             // 49152 -> 4 CTAs/SM

// Unit-normalized fp16 copies (no runtime allocation allowed)
__device__ __half g_A[(size_t)M_DIM * D_DIM];   // ~50 MB
__device__ __half g_B[(size_t)N_DIM * D_DIM];   // ~2.4 MB

// ---------------- PTX helpers (base PTX only) ----------------
__device__ __forceinline__ uint32_t smem_u32(const void* p) {
    uint32_t a;
    asm("{ .reg .u64 t; cvta.to.shared.u64 t, %1; cvt.u32.u64 %0, t; }"
        : "=r"(a) : "l"(p));
    return a;
}

#define CP_ASYNC16(s, g) \
    asm volatile("cp.async.cg.shared.global [%0], [%1], 16;" \
                 :: "r"(s), "l"(g) : "memory")
#define CP_COMMIT() asm volatile("cp.async.commit_group;" ::: "memory")
#define CP_WAIT(n)  asm volatile("cp.async.wait_group %0;" :: "n"(n) : "memory")

#define LDMATRIX_X4(r, addr) \
    asm volatile("ldmatrix.sync.aligned.m8n8.x4.shared.b16 {%0,%1,%2,%3}, [%4];" \
                 : "=r"((r)[0]), "=r"((r)[1]), "=r"((r)[2]), "=r"((r)[3]) \
                 : "r"(addr))

#define MMA16816(d, a, b0, b1) \
    asm volatile("mma.sync.aligned.m16n8k16.row.col.f32.f16.f16.f32 " \
                 "{%0,%1,%2,%3}, {%4,%5,%6,%7}, {%8,%9}, {%0,%1,%2,%3};" \
                 : "+f"((d)[0]), "+f"((d)[1]), "+f"((d)[2]), "+f"((d)[3]) \
                 : "r"((a)[0]), "r"((a)[1]), "r"((a)[2]), "r"((a)[3]), \
                   "r"(b0), "r"(b1))

// Sign-aware float atomic max (out initialized to -1.0; values in [-1, 1])
__device__ __forceinline__ void atomicMaxF(float* addr, float v) {
    if (v >= 0.0f) atomicMax((int*)addr, __float_as_int(v));
    else           atomicMin((unsigned int*)addr, __float_as_uint(v));
}

// Swizzled byte offset inside a tile: row r (128B rows), 16B chunk c in 0..7
__device__ __forceinline__ uint32_t swz(int r, int c) {
    return (uint32_t)(r * 128 + ((c ^ (r & 7)) << 4));
}

// ---------------- fused prep: out init + unit-norm fp16 for A and B ----------
// One warp per row; rows [0, M) -> embed->g_A, rows [M, M+N) -> label->g_B.
__global__ void prep_kernel(const float* __restrict__ embed,
                            const float* __restrict__ label,
                            float* __restrict__ out) {
    int gtid = blockIdx.x * blockDim.x + threadIdx.x;
    if (gtid < B_DIM * L_DIM) out[gtid] = -1.0f;
    int w = gtid >> 5;
    int lane = threadIdx.x & 31;
    const float* src;
    __half* dst;
    if (w < M_DIM)                 { src = embed + (size_t)w * D_DIM;
                                     dst = g_A + (size_t)w * D_DIM; }
    else if (w < M_DIM + N_DIM)    { src = label + (size_t)(w - M_DIM) * D_DIM;
                                     dst = g_B + (size_t)(w - M_DIM) * D_DIM; }
    else return;

    const float4* p = reinterpret_cast<const float4*>(src);
    float4 v[6];
    float s = 0.0f;
#pragma unroll
    for (int j = 0; j < 6; j++) {
        v[j] = p[lane + 32 * j];
        s += v[j].x * v[j].x + v[j].y * v[j].y + v[j].z * v[j].z + v[j].w * v[j].w;
    }
#pragma unroll
    for (int o = 16; o > 0; o >>= 1) s += __shfl_xor_sync(0xffffffffu, s, o);
    float inv = 1.0f / sqrtf(s);   // norms ~27.7, eps clamp never active
#pragma unroll
    for (int j = 0; j < 6; j++) {
        __half2 h0 = __floats2half2_rn(v[j].x * inv, v[j].y * inv);
        __half2 h1 = __floats2half2_rn(v[j].z * inv, v[j].w * inv);
        size_t base = (size_t)(lane + 32 * j) * 4;
        *reinterpret_cast<__half2*>(dst + base)     = h0;
        *reinterpret_cast<__half2*>(dst + base + 2) = h1;
    }
}

// ---------------- fused HMMA GEMM + max epilogue ----------------
// C[128 x 64] tile of cos = unitA . unitB^T; max over v per label,
// atomicMax into out[b][l] (atomics reduce over s across tiles).
// 2-stage pipeline, ONE barrier per chunk:
//   iter c: compute(c); wait(chunk c+1); sync; load(c+2) into stage c&1.
__global__ __launch_bounds__(NTHREADS)
void gemm_mma_kernel(const __half* __restrict__ A, const __half* __restrict__ Bm,
                     float* __restrict__ out) {
    extern __shared__ char smem[];
    const uint32_t sb = smem_u32(smem);
    const int tid = threadIdx.x;
    const int wid = tid >> 5;
    const int lane = tid & 31;
    const int wm = wid >> 1;            // 0..1  (m: 64-row slab)
    const int wn = wid & 1;             // 0..1  (n: 32-col slab)
    const int m0 = blockIdx.y * BM;
    const int n0 = blockIdx.x * BN;
    const int l0 = blockIdx.x * (BN / V_DIM);

    auto loadChunk = [&](int stage, int c) {
        const uint32_t base = sb + stage * BUF_BYTES;
#pragma unroll
        for (int j = 0; j < 8; j++) {                  // A: 128 rows x 128B
            int f = j * NTHREADS + tid;
            int r = f >> 3, cc = f & 7;
            const __half* g = A + (size_t)(m0 + r) * D_DIM + c * KC + cc * 8;
            CP_ASYNC16(base + swz(r, cc), g);
        }
#pragma unroll
        for (int j = 0; j < 4; j++) {                  // B: 64 rows x 128B
            int f = j * NTHREADS + tid;
            int r = f >> 3, cc = f & 7;
            const __half* g = Bm + (size_t)(n0 + r) * D_DIM + c * KC + cc * 8;
            CP_ASYNC16(base + A_BYTES + swz(r, cc), g);
        }
    };

    float acc[4][4][4];
#pragma unroll
    for (int mi = 0; mi < 4; mi++)
#pragma unroll
        for (int ni = 0; ni < 4; ni++)
#pragma unroll
            for (int e = 0; e < 4; e++) acc[mi][ni][e] = 0.0f;

    loadChunk(0, 0); CP_COMMIT();
    loadChunk(1, 1); CP_COMMIT();
    CP_WAIT(1);            // chunk 0 complete (chunk 1 still in flight)
    __syncthreads();       // chunk 0 visible to all warps

    const int t = lane >> 3;            // ldmatrix tile index 0..3
    const int lr = lane & 7;            // row within 8-row tile

#pragma unroll 1
    for (int c = 0; c < NCHUNK; c++) {
        const uint32_t ab = sb + (c & 1) * BUF_BYTES;
        const uint32_t bb = ab + A_BYTES;
#pragma unroll
        for (int ks = 0; ks < 4; ks++) {          // four k16 steps per chunk
            uint32_t afr[4][4], bfr[2][4];
#pragma unroll
            for (int mi = 0; mi < 4; mi++) {
                int r = wm * 64 + mi * 16 + lr + ((t & 1) << 3);
                int cc = ks * 2 + (t >> 1);
                LDMATRIX_X4(afr[mi], ab + swz(r, cc));
            }
#pragma unroll
            for (int p = 0; p < 2; p++) {
                int r = wn * 32 + p * 16 + lr + ((t >> 1) << 3);
                int cc = ks * 2 + (t & 1);
                LDMATRIX_X4(bfr[p], bb + swz(r, cc));
            }
#pragma unroll
            for (int mi = 0; mi < 4; mi++)
#pragma unroll
                for (int ni = 0; ni < 4; ni++)
                    MMA16816(acc[mi][ni], afr[mi],
                             bfr[ni >> 1][(ni & 1) * 2], bfr[ni >> 1][(ni & 1) * 2 + 1]);
        }

        if (c + 1 < NCHUNK) {
            CP_WAIT(0);        // chunk c+1 complete (loaded one chunk ago)
            __syncthreads();   // (a) c+1 visible; (b) all warps done with stage c&1
            if (c + 2 < NCHUNK) { loadChunk(c & 1, c + 2); CP_COMMIT(); }
        }
    }

    // ---- epilogue: each n8 fragment == one label; reduce v via shfl ----
    const int g  = lane >> 2;           // fragment row group 0..7
    const int tq = lane & 3;            // v-pair owner 0..3
#pragma unroll
    for (int mi = 0; mi < 4; mi++) {
        const int b0 = wm * 64 + mi * 16 + g;      // local row == batch b
#pragma unroll
        for (int ni = 0; ni < 4; ni++) {
            float mx0 = fmaxf(acc[mi][ni][0], acc[mi][ni][1]);   // row b0
            float mx1 = fmaxf(acc[mi][ni][2], acc[mi][ni][3]);   // row b0+8
#pragma unroll
            for (int o = 1; o < 4; o <<= 1) {      // collect all 8 v of this label
                mx0 = fmaxf(mx0, __shfl_xor_sync(0xffffffffu, mx0, o));
                mx1 = fmaxf(mx1, __shfl_xor_sync(0xffffffffu, mx1, o));
            }
            if (tq == 0) {
                int l = l0 + wn * 4 + ni;
                atomicMaxF(out + b0 * L_DIM + l, mx0);
                atomicMaxF(out + (b0 + 8) * L_DIM + l, mx1);
            }
        }
    }
}

extern "C" void kernel_launch(void* const* d_in, const int* in_sizes, int n_in,
                              void* d_out, int out_size) {
    const float* embed = (const float*)d_in[0];   // [256,128,768]
    const float* label = (const float*)d_in[1];   // [200,8,768]
    float* out = (float*)d_out;                   // [128,200]

    __half *d_A, *d_B;
    cudaGetSymbolAddress((void**)&d_A, g_A);
    cudaGetSymbolAddress((void**)&d_B, g_B);

    (void)cudaFuncSetAttribute(gemm_mma_kernel,
                               cudaFuncAttributeMaxDynamicSharedMemorySize,
                               SMEM_TOTAL);

    // one prep launch: out init + A normalize + B normalize (8 warps/block)
    prep_kernel<<<(M_DIM + N_DIM) / 8, 256>>>(embed, label, out);

    dim3 grid(N_DIM / BN, M_DIM / BM);   // (25, 256) = 6400 CTAs
    gemm_mma_kernel<<<grid, NTHREADS, SMEM_TOTAL>>>(d_A, d_B, out);
}